// round 16
// baseline (speedup 1.0000x reference)
#include <cuda_runtime.h>
#include <math.h>

// Problem constants: B=4, S=4096, H=2048, E=8, K=2
#define T_TOKENS 16384
#define HDIM     2048
#define NEXP     8
#define TOPK     2
#define H4       (HDIM / 4)    // 512 float4 per row
#define TPC      32            // tokens per CTA
#define DEPTH    4             // ring slots
#define NSTAGE   32            // stages: 16 float4 of H per token per stage

// Zero-initialized at module load; last block re-zeros after each use so
// every graph replay sees a clean state (deterministic).
__device__ int g_counts[NEXP];
__device__ unsigned int g_done;

// Warp-specialized streaming: 2 producer warps stream all 32 token rows
// GMEM->SMEM ring via batched __ldcg + STS (in-flight bytes come from the
// producers' free registers, not the consumers'), 4 consumer warps run the
// verified R7 math (8 tokens each, half-warp expert split) reading x from
// smem. Ring: 4 slots x 8KB, full/empty mbarriers, XOR-swizzled STS.
// 512 CTAs x 192 threads, single wave at 4 CTAs/SM.
__global__ __launch_bounds__(192, 4)
void router_kernel(const float* __restrict__ x,
                   const float* __restrict__ gate_w,
                   float* __restrict__ out) {
    __shared__ float4 s_x[DEPTH][TPC][16];                 // 32 KB
    __shared__ __align__(8) unsigned long long s_full[DEPTH], s_empty[DEPTH];
    __shared__ int s_counts[NEXP];

    const int tid = threadIdx.x;
    if (tid < NEXP) s_counts[tid] = 0;
    if (tid == 0) {
        #pragma unroll
        for (int k = 0; k < DEPTH; k++) {
            unsigned f = (unsigned)__cvta_generic_to_shared(&s_full[k]);
            unsigned e = (unsigned)__cvta_generic_to_shared(&s_empty[k]);
            asm volatile("mbarrier.init.shared.b64 [%0], %1;" :: "r"(f), "r"(64)  : "memory");
            asm volatile("mbarrier.init.shared.b64 [%0], %1;" :: "r"(e), "r"(128) : "memory");
        }
    }
    __syncthreads();

    const int lane  = tid & 31;
    const int wid   = tid >> 5;
    const int tbase = blockIdx.x * TPC;
    const float4* __restrict__ x4 = (const float4*)x;

#define MBAR_WAIT(ADDR, PAR)                                                  \
    do {                                                                      \
        unsigned _done;                                                       \
        asm volatile(                                                         \
            "{\n\t.reg .pred p;\n\t"                                          \
            "mbarrier.try_wait.parity.acquire.cta.shared::cta.b64 p, [%1], %2;\n\t" \
            "selp.b32 %0, 1, 0, p;\n\t}"                                      \
            : "=r"(_done) : "r"(ADDR), "r"(PAR) : "memory");                   \
        if (!_done) {                                                         \
            asm volatile(                                                     \
                "{\n\t.reg .pred P1;\n\t"                                     \
                "WL_%=:\n\t"                                                  \
                "mbarrier.try_wait.parity.acquire.cta.shared::cta.b64 P1, [%0], %1, 0x989680;\n\t" \
                "@P1 bra.uni WD_%=;\n\t"                                      \
                "bra.uni WL_%=;\n\t"                                          \
                "WD_%=:\n\t}"                                                 \
                :: "r"(ADDR), "r"(PAR) : "memory");                           \
        }                                                                     \
    } while (0)

#define MBAR_ARRIVE(ADDR)                                                     \
    asm volatile("mbarrier.arrive.release.cta.shared::cta.b64 _, [%0];"       \
                 :: "r"(ADDR) : "memory")

    unsigned full_a[DEPTH], empty_a[DEPTH];
    #pragma unroll
    for (int k = 0; k < DEPTH; k++) {
        full_a[k]  = (unsigned)__cvta_generic_to_shared(&s_full[k]);
        empty_a[k] = (unsigned)__cvta_generic_to_shared(&s_empty[k]);
    }

    if (wid >= 4) {
        // ───────── producer warps (wid 4,5): stream 16 token rows each ─────────
        const int pw   = wid - 4;
        const int tokl = pw * 16 + (lane >> 1);        // CTA-local token 0..31
        const int pb   = (lane & 1) * 8;               // f4 position base 0/8
        const int sw   = tokl & 15;                    // swizzle key
        const float4* __restrict__ src = x4 + (size_t)(tbase + tokl) * H4 + pb;

        #pragma unroll 1
        for (int s = 0; s < NSTAGE; s++) {
            const int slot = s & (DEPTH - 1);
            const unsigned par = 1u ^ (unsigned)((s >> 2) & 1);
            MBAR_WAIT(empty_a[slot], par);

            float4 b[8];
            #pragma unroll
            for (int q = 0; q < 8; q++)
                b[q] = __ldcg(src + 16 * s + q);
            #pragma unroll
            for (int q = 0; q < 8; q++)
                s_x[slot][tokl][(pb + q) ^ sw] = b[q];

            MBAR_ARRIVE(full_a[slot]);
        }
    } else {
        // ───────── consumer warps (wid 0..3): R7 math, x from smem ─────────
        const int l4    = lane & 15;
        const int ebase = (lane >> 4) * 4;
        const int cw    = wid;
        const int t0    = tbase + cw * 8;
        const float4* __restrict__ w4 = (const float4*)gate_w;

        float acc[8 * 4];
        #pragma unroll
        for (int p = 0; p < 32; p++) acc[p] = 0.0f;

        #pragma unroll 1
        for (int s = 0; s < NSTAGE; s++) {
            const int slot = s & (DEPTH - 1);
            const unsigned par = (unsigned)((s >> 2) & 1);
            MBAR_WAIT(full_a[slot], par);

            const int i = l4 + 16 * s;
            float4 wv[4];
            #pragma unroll
            for (int j = 0; j < 4; j++)
                wv[j] = __ldg(w4 + (size_t)(ebase + j) * H4 + i);

            #pragma unroll
            for (int m = 0; m < 8; m++) {
                const int tokl = cw * 8 + m;
                const float4 xv = s_x[slot][tokl][l4 ^ (tokl & 15)];
                #pragma unroll
                for (int j = 0; j < 4; j++) {
                    acc[m * 4 + j] = fmaf(xv.x, wv[j].x, acc[m * 4 + j]);
                    acc[m * 4 + j] = fmaf(xv.y, wv[j].y, acc[m * 4 + j]);
                    acc[m * 4 + j] = fmaf(xv.z, wv[j].z, acc[m * 4 + j]);
                    acc[m * 4 + j] = fmaf(xv.w, wv[j].w, acc[m * 4 + j]);
                }
            }
            MBAR_ARRIVE(empty_a[slot]);
        }

        // Halving reduction over 32 partials within each 16-lane half-warp
        // (verified in R7; static indices only).
        float a[32];
        #pragma unroll
        for (int p = 0; p < 32; p++) a[p] = acc[p];
#define RED_LEVEL(O, L2)                                                   \
        _Pragma("unroll")                                                  \
        for (int j = 0; j < (L2); j++) {                                   \
            float mine  = (lane & (O)) ? a[j + (L2)] : a[j];               \
            float yours = (lane & (O)) ? a[j] : a[j + (L2)];               \
            a[j] = mine + __shfl_xor_sync(0xFFFFFFFFu, yours, (O));        \
        }
        RED_LEVEL(8, 16)
        RED_LEVEL(4, 8)
        RED_LEVEL(2, 4)
        RED_LEVEL(1, 2)
#undef RED_LEVEL

        const int tok = lane >> 2;
        float l[NEXP];
        l[0] = __shfl_sync(0xFFFFFFFFu, a[0], 2 * tok);
        l[1] = __shfl_sync(0xFFFFFFFFu, a[1], 2 * tok);
        l[2] = __shfl_sync(0xFFFFFFFFu, a[0], 2 * tok + 1);
        l[3] = __shfl_sync(0xFFFFFFFFu, a[1], 2 * tok + 1);
        l[4] = __shfl_sync(0xFFFFFFFFu, a[0], 16 + 2 * tok);
        l[5] = __shfl_sync(0xFFFFFFFFu, a[1], 16 + 2 * tok);
        l[6] = __shfl_sync(0xFFFFFFFFu, a[0], 17 + 2 * tok);
        l[7] = __shfl_sync(0xFFFFFFFFu, a[1], 17 + 2 * tok);

        if ((lane & 3) == 0) {
            const int t = t0 + tok;

            // top-1 (strict > keeps lowest index on tie, matching jax top_k)
            float m1 = l[0]; int i1 = 0;
            #pragma unroll
            for (int e = 1; e < NEXP; e++)
                if (l[e] > m1) { m1 = l[e]; i1 = e; }
            // top-2
            float m2 = -INFINITY; int i2 = 0;
            #pragma unroll
            for (int e = 0; e < NEXP; e++)
                if (e != i1 && l[e] > m2) { m2 = l[e]; i2 = e; }

            // renormalized top-2 softmax weights
            float e2  = __expf(m2 - m1);    // <= 1, numerically safe
            float inv = 1.0f / (1.0f + e2);

            out[(size_t)t * TOPK + 0] = inv;
            out[(size_t)t * TOPK + 1] = e2 * inv;
            out[(size_t)T_TOKENS * TOPK + (size_t)t * TOPK + 0] = (float)i1;
            out[(size_t)T_TOKENS * TOPK + (size_t)t * TOPK + 1] = (float)i2;

            atomicAdd(&s_counts[i1], 1);
            atomicAdd(&s_counts[i2], 1);
        }
    }

    __syncthreads();
    if (tid < NEXP)
        atomicAdd(&g_counts[tid], s_counts[tid]);
    __threadfence();
    __syncthreads();

    // Last block computes the aux loss and resets global state.
    if (tid == 0) {
        unsigned int prev = atomicAdd(&g_done, 1u);
        if (prev == gridDim.x - 1) {
            volatile int* vc = (volatile int*)g_counts;
            float mpe[NEXP];
            float mu = 0.0f;
            #pragma unroll
            for (int e = 0; e < NEXP; e++) {
                mpe[e] = (float)vc[e] / (float)T_TOKENS;
                mu += mpe[e];
            }
            mu *= (1.0f / NEXP);
            float v = 0.0f;
            #pragma unroll
            for (int e = 0; e < NEXP; e++) {
                float d = mpe[e] - mu;
                v += d * d;
            }
            v *= (1.0f / (NEXP - 1));   // unbiased variance (ddof=1)
            out[(size_t)T_TOKENS * TOPK * 2] = v * (float)NEXP;

            // Reset for the next graph replay.
            #pragma unroll
            for (int e = 0; e < NEXP; e++) g_counts[e] = 0;
            g_done = 0u;
        }
    }
#undef MBAR_WAIT
#undef MBAR_ARRIVE
}

extern "C" void kernel_launch(void* const* d_in, const int* in_sizes, int n_in,
                              void* d_out, int out_size) {
    const float* x      = (const float*)d_in[0];   // (B,S,H) = (T, H)
    const float* gate_w = (const float*)d_in[1];   // (E, H)
    float* out = (float*)d_out;

    router_kernel<<<T_TOKENS / TPC, 192>>>(x, gate_w, out);
}

// round 17
// speedup vs baseline: 2.3034x; 2.3034x over previous
#include <cuda_runtime.h>
#include <cuda_bf16.h>
#include <math.h>

// Problem constants: B=4, S=4096, H=2048, E=8, K=2
#define T_TOKENS 16384
#define HDIM     2048
#define NEXP     8
#define TOPK     2
#define H4       (HDIM / 4)   // 512 float4 per row
#define TPW      8            // tokens per warp
#define NITER    (H4 / 16)    // 32: each half-warp covers 16 float4 per iter

// Zero-initialized at module load; last block re-zeros after each use so
// every graph replay sees a clean state (deterministic).
__device__ int g_counts[NEXP];
__device__ unsigned int g_done;

// One warp = 8 tokens. Half-warp expert split: lanes 0-15 own experts 0-3,
// lanes 16-31 own experts 4-7. x uses a register double-buffer prefetch
// (distance 1). The prefetch is INTERLEAVED: each of the 4 expert blocks
// issues 1 w-load + 2 x-prefetch loads before its 32 FMAs, spreading LSU
// and L1tex pressure across the iteration instead of a 12-deep front batch
// (convoy relief at the 4cyc/LDG LSU accept floor).
// 1024 CTAs x 64 threads = 2048 warps = T/8 groups, single balanced wave.
__global__ __launch_bounds__(64, 8)
void router_kernel(const float* __restrict__ x,
                   const float* __restrict__ gate_w,
                   float* __restrict__ out) {
    __shared__ int s_counts[NEXP];
    if (threadIdx.x < NEXP) s_counts[threadIdx.x] = 0;
    __syncthreads();

    const int lane        = threadIdx.x & 31;
    const int l4          = lane & 15;        // position within half-warp
    const int ebase       = (lane >> 4) * 4;  // this half-warp's expert base
    const int warp_global = (blockIdx.x * blockDim.x + threadIdx.x) >> 5;
    const int t0          = warp_global * TPW;

    const float4* __restrict__ x4 = (const float4*)x;
    const float4* __restrict__ w4 = (const float4*)gate_w;
    const float4* __restrict__ xb0 = x4 + (size_t)t0 * H4 + l4;  // token 0, iter 0

    // acc[m*4 + j] : token m, local expert j (32 regs)
    float acc[TPW * 4];
    #pragma unroll
    for (int p = 0; p < TPW * 4; p++) acc[p] = 0.0f;

    float4 xa[TPW], xb[TPW];

    // Prologue: load iteration 0's x into buffer A.
    #pragma unroll
    for (int m = 0; m < TPW; m++)
        xa[m] = __ldg(xb0 + (size_t)m * H4);

    // One step: per expert block j, issue w-load + 2 x-prefetch loads, then
    // that block's FMAs. Loads stay spread through the iteration.
#define STEP(CUR, NXT, IT)                                                   \
    do {                                                                     \
        const int _nit = (IT) + 1;                                           \
        const int _i = l4 + 16 * (IT);                                       \
        _Pragma("unroll")                                                    \
        for (int j = 0; j < 4; j++) {                                        \
            float4 wv = __ldg(w4 + (size_t)(ebase + j) * H4 + _i);           \
            if (_nit < NITER) {                                              \
                NXT[2 * j] = __ldg(xb0 + (size_t)(2 * j) * H4 + 16 * _nit);  \
                NXT[2 * j + 1] =                                             \
                    __ldg(xb0 + (size_t)(2 * j + 1) * H4 + 16 * _nit);       \
            }                                                                \
            _Pragma("unroll")                                                \
            for (int m = 0; m < TPW; m++) {                                  \
                acc[m * 4 + j] = fmaf(CUR[m].x, wv.x, acc[m * 4 + j]);       \
                acc[m * 4 + j] = fmaf(CUR[m].y, wv.y, acc[m * 4 + j]);       \
                acc[m * 4 + j] = fmaf(CUR[m].z, wv.z, acc[m * 4 + j]);       \
                acc[m * 4 + j] = fmaf(CUR[m].w, wv.w, acc[m * 4 + j]);       \
            }                                                                \
        }                                                                    \
    } while (0)

    #pragma unroll 1
    for (int it2 = 0; it2 < NITER / 2; it2++) {
        STEP(xa, xb, 2 * it2);
        STEP(xb, xa, 2 * it2 + 1);
    }
#undef STEP

    // Halving reduction over 32 partials within each 16-lane half-warp
    // (static indices only; offsets <=8 never cross the half-warp).
    // Result: lane l4 holds a[0] = sum(group 2*l4), a[1] = sum(group 2*l4+1),
    // group = tok*4 + local_expert.
    float a[32];
    #pragma unroll
    for (int p = 0; p < 32; p++) a[p] = acc[p];
#define RED_LEVEL(O, L2)                                                   \
    _Pragma("unroll")                                                      \
    for (int j = 0; j < (L2); j++) {                                       \
        float mine  = (lane & (O)) ? a[j + (L2)] : a[j];                   \
        float yours = (lane & (O)) ? a[j] : a[j + (L2)];                   \
        a[j] = mine + __shfl_xor_sync(0xFFFFFFFFu, yours, (O));            \
    }
    RED_LEVEL(8, 16)
    RED_LEVEL(4, 8)
    RED_LEVEL(2, 4)
    RED_LEVEL(1, 2)
#undef RED_LEVEL

    // Lane (hw, l4) holds token l4>>1, experts ebase + 2*(l4&1) + {0,1}.
    // Gather token t's 8 logits: lanes 2t, 2t+1 (experts 0-3) and
    // 16+2t, 17+2t (experts 4-7). Every lane rebuilds its token t = lane>>2.
    const int tok = lane >> 2;
    float l[NEXP];
    l[0] = __shfl_sync(0xFFFFFFFFu, a[0], 2 * tok);
    l[1] = __shfl_sync(0xFFFFFFFFu, a[1], 2 * tok);
    l[2] = __shfl_sync(0xFFFFFFFFu, a[0], 2 * tok + 1);
    l[3] = __shfl_sync(0xFFFFFFFFu, a[1], 2 * tok + 1);
    l[4] = __shfl_sync(0xFFFFFFFFu, a[0], 16 + 2 * tok);
    l[5] = __shfl_sync(0xFFFFFFFFu, a[1], 16 + 2 * tok);
    l[6] = __shfl_sync(0xFFFFFFFFu, a[0], 17 + 2 * tok);
    l[7] = __shfl_sync(0xFFFFFFFFu, a[1], 17 + 2 * tok);

    if ((lane & 3) == 0) {
        const int t = t0 + tok;

        // top-1 (strict > keeps lowest index on tie, matching jax top_k)
        float m1 = l[0]; int i1 = 0;
        #pragma unroll
        for (int e = 1; e < NEXP; e++)
            if (l[e] > m1) { m1 = l[e]; i1 = e; }
        // top-2
        float m2 = -INFINITY; int i2 = 0;
        #pragma unroll
        for (int e = 0; e < NEXP; e++)
            if (e != i1 && l[e] > m2) { m2 = l[e]; i2 = e; }

        // renormalized top-2 softmax weights
        float e2  = __expf(m2 - m1);    // <= 1, numerically safe
        float inv = 1.0f / (1.0f + e2);

        out[(size_t)t * TOPK + 0] = inv;
        out[(size_t)t * TOPK + 1] = e2 * inv;
        out[(size_t)T_TOKENS * TOPK + (size_t)t * TOPK + 0] = (float)i1;
        out[(size_t)T_TOKENS * TOPK + (size_t)t * TOPK + 1] = (float)i2;

        atomicAdd(&s_counts[i1], 1);
        atomicAdd(&s_counts[i2], 1);
    }

    __syncthreads();
    if (threadIdx.x < NEXP)
        atomicAdd(&g_counts[threadIdx.x], s_counts[threadIdx.x]);
    __threadfence();
    __syncthreads();

    // Last block computes the aux loss and resets global state.
    if (threadIdx.x == 0) {
        unsigned int prev = atomicAdd(&g_done, 1u);
        if (prev == gridDim.x - 1) {
            volatile int* vc = (volatile int*)g_counts;
            float mpe[NEXP];
            float mu = 0.0f;
            #pragma unroll
            for (int e = 0; e < NEXP; e++) {
                mpe[e] = (float)vc[e] / (float)T_TOKENS;
                mu += mpe[e];
            }
            mu *= (1.0f / NEXP);
            float v = 0.0f;
            #pragma unroll
            for (int e = 0; e < NEXP; e++) {
                float d = mpe[e] - mu;
                v += d * d;
            }
            v *= (1.0f / (NEXP - 1));   // unbiased variance (ddof=1)
            out[(size_t)T_TOKENS * TOPK * 2] = v * (float)NEXP;

            // Reset for the next graph replay.
            #pragma unroll
            for (int e = 0; e < NEXP; e++) g_counts[e] = 0;
            g_done = 0u;
        }
    }
}

extern "C" void kernel_launch(void* const* d_in, const int* in_sizes, int n_in,
                              void* d_out, int out_size) {
    const float* x      = (const float*)d_in[0];   // (B,S,H) = (T, H)
    const float* gate_w = (const float*)d_in[1];   // (E, H)
    float* out = (float*)d_out;

    router_kernel<<<1024, 64>>>(x, gate_w, out);
}